// round 1
// baseline (speedup 1.0000x reference)
#include <cuda_runtime.h>
#include <cuda_bf16.h>
#include <math.h>

// Problem constants (fixed by the reference)
#define B_  4
#define T_  4096
#define D_  2048
#define M_  512

// Scratch: v / wv buffer [B, T, M] fp32 (wv overwrites v in place)
__device__ float g_v[(size_t)B_ * T_ * M_];

// ---------------------------------------------------------------------------
// Tiled SGEMM (NT form): C[N, Mo] = concat(A1,A2)[N, K1+K2] * B[Mo, ldb]^T
//   + bias[Mo] (+ resid[N, Mo] if non-null)
// A1 row-major [N, K1], A2 row-major [N, K2], B row-major with row stride ldb
// Requires: N % 128 == 0, Mo % 128 == 0, K1 % 16 == 0, K2 % 16 == 0
// ---------------------------------------------------------------------------
#define BM 128
#define BN 128
#define BK 16
#define TM 8
#define TN 8

__global__ __launch_bounds__(256)
void sgemm_nt(const float* __restrict__ A1, int K1,
              const float* __restrict__ A2, int K2,
              const float* __restrict__ Bm, int ldb,
              const float* __restrict__ bias,
              const float* __restrict__ resid,
              float* __restrict__ C,
              int N, int Mo)
{
    const int K = K1 + K2;
    __shared__ float As[BK][BM + 4];
    __shared__ float Bs[BK][BN + 4];

    const int n0 = blockIdx.y * BM;
    const int m0 = blockIdx.x * BN;
    const int tid = threadIdx.x;
    const int tx = tid & 15;   // 0..15 -> N-tile columns (Mo direction)
    const int ty = tid >> 4;   // 0..15 -> M-tile rows (N direction)

    float acc[TM][TN];
    #pragma unroll
    for (int i = 0; i < TM; i++)
        #pragma unroll
        for (int j = 0; j < TN; j++) acc[i][j] = 0.0f;

    for (int k0 = 0; k0 < K; k0 += BK) {
        // --- load A tile (128 rows x 16 k) as 512 float4 slots, store transposed
        #pragma unroll
        for (int it = 0; it < 2; it++) {
            int s   = tid + it * 256;
            int row = s >> 2;          // 0..127
            int kq  = (s & 3) << 2;    // 0,4,8,12
            int gk  = k0 + kq;
            float4 val;
            if (gk < K1) {
                val = *(const float4*)(A1 + (size_t)(n0 + row) * K1 + gk);
            } else {
                val = *(const float4*)(A2 + (size_t)(n0 + row) * K2 + (gk - K1));
            }
            As[kq + 0][row] = val.x;
            As[kq + 1][row] = val.y;
            As[kq + 2][row] = val.z;
            As[kq + 3][row] = val.w;
        }
        // --- load B tile (128 rows x 16 k)
        #pragma unroll
        for (int it = 0; it < 2; it++) {
            int s   = tid + it * 256;
            int row = s >> 2;
            int kq  = (s & 3) << 2;
            float4 val = *(const float4*)(Bm + (size_t)(m0 + row) * ldb + k0 + kq);
            Bs[kq + 0][row] = val.x;
            Bs[kq + 1][row] = val.y;
            Bs[kq + 2][row] = val.z;
            Bs[kq + 3][row] = val.w;
        }
        __syncthreads();

        #pragma unroll
        for (int k = 0; k < BK; k++) {
            float a[TM], b[TN];
            #pragma unroll
            for (int i = 0; i < TM; i++) a[i] = As[k][ty * TM + i];
            #pragma unroll
            for (int j = 0; j < TN; j++) b[j] = Bs[k][tx * TN + j];
            #pragma unroll
            for (int i = 0; i < TM; i++)
                #pragma unroll
                for (int j = 0; j < TN; j++)
                    acc[i][j] = fmaf(a[i], b[j], acc[i][j]);
        }
        __syncthreads();
    }

    // --- epilogue: bias (+ residual), write C
    #pragma unroll
    for (int i = 0; i < TM; i++) {
        int n = n0 + ty * TM + i;
        #pragma unroll
        for (int j = 0; j < TN; j++) {
            int m = m0 + tx * TN + j;
            float cv = acc[i][j] + bias[m];
            if (resid) cv += resid[(size_t)n * Mo + m];
            C[(size_t)n * Mo + m] = cv;
        }
    }
}

// ---------------------------------------------------------------------------
// Sequential recurrence over T, one thread per (b, m).
//   wv_t = v_t + s * first;  s = s * decay + v_t
// Reads v from g_v and overwrites it with wv in place.
// ---------------------------------------------------------------------------
__global__ void recurrence_kernel(const float* __restrict__ memory_state,
                                  const float* __restrict__ time_decay,
                                  const float* __restrict__ time_first,
                                  float* __restrict__ next_mem)
{
    int id = blockIdx.x * blockDim.x + threadIdx.x;
    if (id >= B_ * M_) return;
    int b = id / M_;
    int m = id % M_;

    float dec   = 1.0f / (1.0f + expf(-time_decay[m])) * 0.9f + 0.1f;
    float first = 1.0f / (1.0f + expf(-time_first[m]));
    float s = memory_state[(size_t)b * M_ + m];

    float* vp = g_v + (size_t)b * T_ * M_ + m;
    #pragma unroll 4
    for (int t = 0; t < T_; t++) {
        float vt = vp[(size_t)t * M_];
        vp[(size_t)t * M_] = vt + s * first;
        s = s * dec + vt;
    }
    next_mem[id] = s;
}

// ---------------------------------------------------------------------------
extern "C" void kernel_launch(void* const* d_in, const int* in_sizes, int n_in,
                              void* d_out, int out_size)
{
    const float* x   = (const float*)d_in[0];  // [B, T, D]
    const float* mem = (const float*)d_in[1];  // [B, M]
    const float* Wv  = (const float*)d_in[2];  // [M, D]
    const float* bv  = (const float*)d_in[3];  // [M]
    const float* Wg  = (const float*)d_in[4];  // [D, D+M]
    const float* bg  = (const float*)d_in[5];  // [D]
    const float* td  = (const float*)d_in[6];  // [M]
    const float* tf  = (const float*)d_in[7];  // [M]
    float* out = (float*)d_out;                // [B,T,D] output, then [B,M] next_memory

    float* v_ptr = nullptr;
    cudaGetSymbolAddress((void**)&v_ptr, g_v);

    const int N = B_ * T_;   // 16384

    // Stage 1: v = x @ Wv^T + bv   -> g_v [N, M]
    {
        dim3 grid(M_ / BN, N / BM);   // (4, 128)
        sgemm_nt<<<grid, 256>>>(x, D_, nullptr, 0,
                                Wv, D_, bv, nullptr,
                                v_ptr, N, M_);
    }

    // Stage 2: recurrence; wv overwrites g_v, next_memory -> out tail
    {
        float* next_mem = out + (size_t)B_ * T_ * D_;
        recurrence_kernel<<<(B_ * M_ + 127) / 128, 128>>>(mem, td, tf, next_mem);
    }

    // Stage 3: out = x + concat(x, wv) @ Wg^T + bg   -> out [N, D]
    {
        dim3 grid(D_ / BN, N / BM);   // (16, 128)
        sgemm_nt<<<grid, 256>>>(x, D_, v_ptr, M_,
                                Wg, D_ + M_, bg, x,
                                out, N, D_);
    }
}

// round 3
// speedup vs baseline: 3.3638x; 3.3638x over previous
#include <cuda_runtime.h>
#include <cstdint>
#include <math.h>

// Problem constants
#define B_  4
#define T_  4096
#define D_  2048
#define M_  512

#define CHUNK 256
#define NCH   (T_ / CHUNK)          // 16

// Scratch
__device__ __align__(1024) float g_v[(size_t)B_ * T_ * M_];
__device__ float g_part[B_ * NCH * M_];
__device__ float g_init[B_ * NCH * M_];

// ---------------------------------------------------------------------------
// helpers
// ---------------------------------------------------------------------------
__device__ __forceinline__ uint32_t smem_u32(const void* p) {
    uint32_t a;
    asm("{ .reg .u64 t; cvta.to.shared.u64 t, %1; cvt.u32.u64 %0, t; }" : "=r"(a) : "l"(p));
    return a;
}
#define CP_ASYNC(dst_u32, src_ptr) \
    asm volatile("cp.async.cg.shared.global [%0], [%1], 16;" :: "r"(dst_u32), "l"(src_ptr) : "memory")
#define CP_COMMIT() asm volatile("cp.async.commit_group;" ::: "memory")
#define CP_WAIT(n)  asm volatile("cp.async.wait_group %0;" :: "n"(n) : "memory")

__device__ __forceinline__ uint32_t to_tf32(float f) {
    uint32_t r;
    asm("cvt.rna.tf32.f32 %0, %1;" : "=r"(r) : "f"(f));
    return r;
}

#define MMA_TF32(d, a, b) \
    asm volatile("mma.sync.aligned.m16n8k8.row.col.f32.tf32.tf32.f32 " \
        "{%0,%1,%2,%3}, {%4,%5,%6,%7}, {%8,%9}, {%0,%1,%2,%3};" \
        : "+f"((d)[0]), "+f"((d)[1]), "+f"((d)[2]), "+f"((d)[3]) \
        : "r"((a)[0]), "r"((a)[1]), "r"((a)[2]), "r"((a)[3]), \
          "r"((b)[0]), "r"((b)[1]))

// ---------------------------------------------------------------------------
// tf32 mma.sync GEMM: C[N, Mo] = concat(A1,A2)[N, K1+K2] * Bw[Mo, K]^T
//   (+ bias[Mo], + resid if non-null). CTA tile 128x128, BK=32, 3 stages.
// ---------------------------------------------------------------------------
#define BM 128
#define BN 128
#define BK 32
#define STAGES 3
#define LDA (BK + 4)                      // 36 floats per row
#define STAGE_FLOATS ((BM + BN) * LDA)    // 9216
#define SMEM_BYTES (STAGES * STAGE_FLOATS * 4)   // 110592

extern __shared__ float smem[];

__global__ __launch_bounds__(256, 2)
void gemm_mma(const float* __restrict__ A1, int K1,
              const float* __restrict__ A2, int K2,
              const float* __restrict__ Bw,
              const float* __restrict__ bias,
              const float* __restrict__ resid,
              float* __restrict__ C, int ldC)
{
    const int K   = K1 + K2;
    const int NCT = K / BK;
    const int tid = threadIdx.x;
    const int wid  = tid >> 5;
    const int lane = tid & 31;
    const int n0 = blockIdx.y * BM;
    const int m0 = blockIdx.x * BN;
    const int wm = (wid >> 1) * 32;   // warp row offset (0,32,64,96)
    const int wn = (wid & 1) * 64;    // warp col offset (0,64)

    float acc[2][8][4];
    #pragma unroll
    for (int mi = 0; mi < 2; ++mi)
        #pragma unroll
        for (int nj = 0; nj < 8; ++nj)
            #pragma unroll
            for (int q = 0; q < 4; ++q) acc[mi][nj][q] = 0.0f;

    // ---- stage loader
    auto load_tile = [&](int c, int buf) {
        const int k0 = c * BK;
        float* dA = smem + buf * STAGE_FLOATS;
        float* dB = dA + BM * LDA;
        const float* srcA; int lda;
        if (k0 < K1) { srcA = A1 + (size_t)n0 * K1 + k0;        lda = K1; }
        else         { srcA = A2 + (size_t)n0 * K2 + (k0 - K1); lda = K2; }
        #pragma unroll
        for (int it = 0; it < 4; ++it) {
            int s = tid + it * 256;
            int row = s >> 3, q = s & 7;
            CP_ASYNC(smem_u32(dA + row * LDA + q * 4),
                     srcA + (size_t)row * lda + q * 4);
        }
        const float* srcB = Bw + (size_t)m0 * K + k0;
        #pragma unroll
        for (int it = 0; it < 4; ++it) {
            int s = tid + it * 256;
            int row = s >> 3, q = s & 7;
            CP_ASYNC(smem_u32(dB + row * LDA + q * 4),
                     srcB + (size_t)row * K + q * 4);
        }
    };

    // ---- prologue
    #pragma unroll
    for (int c = 0; c < STAGES - 1; ++c) {
        load_tile(c, c);
        CP_COMMIT();
    }

    // ---- main loop
    for (int kt = 0; kt < NCT; ++kt) {
        CP_WAIT(STAGES - 2);
        __syncthreads();

        const float* sA = smem + (kt % STAGES) * STAGE_FLOATS;
        const float* sB = sA + BM * LDA;

        #pragma unroll
        for (int ks = 0; ks < BK / 8; ++ks) {
            uint32_t af[2][4], bf[8][2];
            const int r0 = wm + (lane >> 2);
            const int c0 = ks * 8 + (lane & 3);
            #pragma unroll
            for (int mi = 0; mi < 2; ++mi) {
                const float* p = sA + (size_t)(r0 + mi * 16) * LDA + c0;
                af[mi][0] = to_tf32(p[0]);
                af[mi][1] = to_tf32(p[8 * LDA]);
                af[mi][2] = to_tf32(p[4]);
                af[mi][3] = to_tf32(p[8 * LDA + 4]);
            }
            #pragma unroll
            for (int nj = 0; nj < 8; ++nj) {
                const float* p = sB + (size_t)(wn + nj * 8 + (lane >> 2)) * LDA + c0;
                bf[nj][0] = to_tf32(p[0]);
                bf[nj][1] = to_tf32(p[4]);
            }
            #pragma unroll
            for (int mi = 0; mi < 2; ++mi)
                #pragma unroll
                for (int nj = 0; nj < 8; ++nj)
                    MMA_TF32(acc[mi][nj], af[mi], bf[nj]);
        }
        __syncthreads();

        const int nc = kt + STAGES - 1;
        if (nc < NCT) load_tile(nc, nc % STAGES);
        CP_COMMIT();
    }

    // ---- epilogue: bias (+resid), float2 stores
    #pragma unroll
    for (int mi = 0; mi < 2; ++mi) {
        const int rbase = n0 + wm + mi * 16 + (lane >> 2);
        #pragma unroll
        for (int nj = 0; nj < 8; ++nj) {
            const int col = m0 + wn + nj * 8 + 2 * (lane & 3);
            float2 bb = *(const float2*)(bias + col);
            // rows rbase and rbase+8
            #pragma unroll
            for (int h = 0; h < 2; ++h) {
                const int r = rbase + h * 8;
                float2 v;
                v.x = acc[mi][nj][2 * h + 0] + bb.x;
                v.y = acc[mi][nj][2 * h + 1] + bb.y;
                size_t off = (size_t)r * ldC + col;
                if (resid) {
                    float2 rr = *(const float2*)(resid + off);
                    v.x += rr.x; v.y += rr.y;
                }
                *(float2*)(C + off) = v;
            }
        }
    }
}

// ---------------------------------------------------------------------------
// Recurrence: chunked parallel scan (3 kernels)
//   wv_t = v_t + s_t * first;  s_{t+1} = s_t * dec + v_t
// ---------------------------------------------------------------------------
__global__ void rec_partial(const float* __restrict__ time_decay)
{
    int id = blockIdx.x * blockDim.x + threadIdx.x;   // B*NCH*M threads
    if (id >= B_ * NCH * M_) return;
    int m  = id % M_;
    int ch = (id / M_) % NCH;
    int b  = id / (M_ * NCH);

    float dec = 1.0f / (1.0f + expf(-time_decay[m])) * 0.9f + 0.1f;
    const float* vp = g_v + ((size_t)b * T_ + (size_t)ch * CHUNK) * M_ + m;
    float s = 0.0f;
    #pragma unroll 8
    for (int t = 0; t < CHUNK; ++t)
        s = s * dec + vp[(size_t)t * M_];
    g_part[id] = s;
}

__global__ void rec_combine(const float* __restrict__ memory_state,
                            const float* __restrict__ time_decay,
                            float* __restrict__ next_mem)
{
    int id = blockIdx.x * blockDim.x + threadIdx.x;   // B*M threads
    if (id >= B_ * M_) return;
    int m = id % M_;
    int b = id / M_;

    float dec  = 1.0f / (1.0f + expf(-time_decay[m])) * 0.9f + 0.1f;
    float decC = powf(dec, (float)CHUNK);
    float s = memory_state[id];
    #pragma unroll
    for (int ch = 0; ch < NCH; ++ch) {
        int idx = (b * NCH + ch) * M_ + m;
        g_init[idx] = s;
        s = s * decC + g_part[idx];
    }
    next_mem[id] = s;
}

__global__ void rec_apply(const float* __restrict__ time_decay,
                          const float* __restrict__ time_first)
{
    int id = blockIdx.x * blockDim.x + threadIdx.x;   // B*NCH*M threads
    if (id >= B_ * NCH * M_) return;
    int m  = id % M_;
    int ch = (id / M_) % NCH;
    int b  = id / (M_ * NCH);

    float dec   = 1.0f / (1.0f + expf(-time_decay[m])) * 0.9f + 0.1f;
    float first = 1.0f / (1.0f + expf(-time_first[m]));
    float s = g_init[id];
    float* vp = g_v + ((size_t)b * T_ + (size_t)ch * CHUNK) * M_ + m;
    #pragma unroll 4
    for (int t = 0; t < CHUNK; ++t) {
        float vt = vp[(size_t)t * M_];
        vp[(size_t)t * M_] = vt + s * first;
        s = s * dec + vt;
    }
}

// ---------------------------------------------------------------------------
extern "C" void kernel_launch(void* const* d_in, const int* in_sizes, int n_in,
                              void* d_out, int out_size)
{
    const float* x   = (const float*)d_in[0];  // [B, T, D]
    const float* mem = (const float*)d_in[1];  // [B, M]
    const float* Wv  = (const float*)d_in[2];  // [M, D]
    const float* bv  = (const float*)d_in[3];  // [M]
    const float* Wg  = (const float*)d_in[4];  // [D, D+M]
    const float* bg  = (const float*)d_in[5];  // [D]
    const float* td  = (const float*)d_in[6];  // [M]
    const float* tf  = (const float*)d_in[7];  // [M]
    float* out = (float*)d_out;                // [B,T,D], then [B,M] next_memory

    float* v_ptr = nullptr;
    cudaGetSymbolAddress((void**)&v_ptr, g_v);

    cudaFuncSetAttribute(gemm_mma, cudaFuncAttributeMaxDynamicSharedMemorySize,
                         SMEM_BYTES);

    const int N = B_ * T_;   // 16384

    // Stage 1: v = x @ Wv^T + bv   -> g_v [N, 512]
    {
        dim3 grid(M_ / BN, N / BM);   // (4, 128)
        gemm_mma<<<grid, 256, SMEM_BYTES>>>(x, D_, nullptr, 0,
                                            Wv, bv, nullptr, v_ptr, M_);
    }

    // Stage 2: chunked-scan recurrence (wv overwrites g_v)
    {
        float* next_mem = out + (size_t)B_ * T_ * D_;
        int n1 = B_ * NCH * M_;
        rec_partial<<<(n1 + 255) / 256, 256>>>(td);
        rec_combine<<<(B_ * M_ + 127) / 128, 128>>>(mem, td, next_mem);
        rec_apply<<<(n1 + 255) / 256, 256>>>(td, tf);
    }

    // Stage 3: out = x + concat(x, wv) @ Wg^T + bg   -> out [N, 2048]
    {
        dim3 grid(D_ / BN, N / BM);   // (16, 128)
        gemm_mma<<<grid, 256, SMEM_BYTES>>>(x, D_, v_ptr, M_,
                                            Wg, bg, x, out, D_);
    }
}

// round 4
// speedup vs baseline: 3.4950x; 1.0390x over previous
#include <cuda_runtime.h>
#include <cstdint>
#include <math.h>

// Problem constants
#define B_  4
#define T_  4096
#define D_  2048
#define M_  512

#define CHUNK 128
#define NCH   (T_ / CHUNK)          // 32

// Scratch
__device__ __align__(1024) float g_v[(size_t)B_ * T_ * M_];
__device__ float g_part[B_ * NCH * M_];
__device__ float g_init[B_ * NCH * M_];

// ---------------------------------------------------------------------------
// helpers
// ---------------------------------------------------------------------------
__device__ __forceinline__ uint32_t smem_u32(const void* p) {
    uint32_t a;
    asm("{ .reg .u64 t; cvta.to.shared.u64 t, %1; cvt.u32.u64 %0, t; }" : "=r"(a) : "l"(p));
    return a;
}
#define CP_ASYNC(dst_u32, src_ptr) \
    asm volatile("cp.async.cg.shared.global [%0], [%1], 16;" :: "r"(dst_u32), "l"(src_ptr) : "memory")
#define CP_COMMIT() asm volatile("cp.async.commit_group;" ::: "memory")
#define CP_WAIT(n)  asm volatile("cp.async.wait_group %0;" :: "n"(n) : "memory")

__device__ __forceinline__ uint32_t to_tf32(float f) {
    uint32_t r;
    asm("cvt.rna.tf32.f32 %0, %1;" : "=r"(r) : "f"(f));
    return r;
}

#define MMA_TF32(d, a, b) \
    asm volatile("mma.sync.aligned.m16n8k8.row.col.f32.tf32.tf32.f32 " \
        "{%0,%1,%2,%3}, {%4,%5,%6,%7}, {%8,%9}, {%0,%1,%2,%3};" \
        : "+f"((d)[0]), "+f"((d)[1]), "+f"((d)[2]), "+f"((d)[3]) \
        : "r"((a)[0]), "r"((a)[1]), "r"((a)[2]), "r"((a)[3]), \
          "r"((b)[0]), "r"((b)[1]))

// ---------------------------------------------------------------------------
// tf32 mma.sync GEMM: C[N, Mo] = concat(A1,A2)[N, K1+K2] * Bw[Mo, K]^T
//   (+ bias[Mo], + resid if non-null)
// CTA tile 128x256, 8 warps (2x4), warp tile 64x64, BK=32, 3 stages.
// ---------------------------------------------------------------------------
#define BM 128
#define BN 256
#define BK 32
#define STAGES 3
#define LDA (BK + 4)                      // 36 floats per row (conflict-free)
#define STAGE_FLOATS ((BM + BN) * LDA)    // 13824
#define SMEM_BYTES (STAGES * STAGE_FLOATS * 4)   // 165888

extern __shared__ float smem[];

__global__ __launch_bounds__(256, 1)
void gemm_mma(const float* __restrict__ A1, int K1,
              const float* __restrict__ A2, int K2,
              const float* __restrict__ Bw,
              const float* __restrict__ bias,
              const float* __restrict__ resid,
              float* __restrict__ C, int ldC)
{
    const int K   = K1 + K2;
    const int NCT = K / BK;
    const int tid = threadIdx.x;
    const int wid  = tid >> 5;
    const int lane = tid & 31;
    const int n0 = blockIdx.y * BM;
    const int m0 = blockIdx.x * BN;
    const int wm = (wid >> 2) * 64;   // warp row offset (0, 64)
    const int wn = (wid & 3) * 64;    // warp col offset (0, 64, 128, 192)

    float acc[4][8][4];
    #pragma unroll
    for (int mi = 0; mi < 4; ++mi)
        #pragma unroll
        for (int nj = 0; nj < 8; ++nj)
            #pragma unroll
            for (int q = 0; q < 4; ++q) acc[mi][nj][q] = 0.0f;

    // ---- stage loader
    auto load_tile = [&](int c, int buf) {
        const int k0 = c * BK;
        float* dA = smem + buf * STAGE_FLOATS;
        float* dB = dA + BM * LDA;
        const float* srcA; int lda;
        if (k0 < K1) { srcA = A1 + (size_t)n0 * K1 + k0;        lda = K1; }
        else         { srcA = A2 + (size_t)n0 * K2 + (k0 - K1); lda = K2; }
        #pragma unroll
        for (int it = 0; it < 4; ++it) {       // A: 1024 float4 slots
            int s = tid + it * 256;
            int row = s >> 3, q = s & 7;
            CP_ASYNC(smem_u32(dA + row * LDA + q * 4),
                     srcA + (size_t)row * lda + q * 4);
        }
        const float* srcB = Bw + (size_t)m0 * K + k0;
        #pragma unroll
        for (int it = 0; it < 8; ++it) {       // B: 2048 float4 slots
            int s = tid + it * 256;
            int row = s >> 3, q = s & 7;
            CP_ASYNC(smem_u32(dB + row * LDA + q * 4),
                     srcB + (size_t)row * K + q * 4);
        }
    };

    // ---- prologue: fill 2 stages
    #pragma unroll
    for (int c = 0; c < STAGES - 1; ++c) {
        load_tile(c, c);
        CP_COMMIT();
    }

    // ---- main loop
    for (int kt = 0; kt < NCT; ++kt) {
        CP_WAIT(STAGES - 2);
        __syncthreads();   // buffer (kt+2)%3 fully consumed in iteration kt-1

        // issue next stage loads first, overlapping with this iteration's MMA
        const int nc = kt + STAGES - 1;
        if (nc < NCT) load_tile(nc, nc % STAGES);
        CP_COMMIT();

        const float* sA = smem + (kt % STAGES) * STAGE_FLOATS;
        const float* sB = sA + BM * LDA;

        #pragma unroll
        for (int ks = 0; ks < BK / 8; ++ks) {
            uint32_t af[4][4], bf[8][2];
            const int r0 = wm + (lane >> 2);
            const int c0 = ks * 8 + (lane & 3);
            #pragma unroll
            for (int mi = 0; mi < 4; ++mi) {
                const float* p = sA + (size_t)(r0 + mi * 16) * LDA + c0;
                af[mi][0] = to_tf32(p[0]);
                af[mi][1] = to_tf32(p[8 * LDA]);
                af[mi][2] = to_tf32(p[4]);
                af[mi][3] = to_tf32(p[8 * LDA + 4]);
            }
            #pragma unroll
            for (int nj = 0; nj < 8; ++nj) {
                const float* p = sB + (size_t)(wn + nj * 8 + (lane >> 2)) * LDA + c0;
                bf[nj][0] = to_tf32(p[0]);
                bf[nj][1] = to_tf32(p[4]);
            }
            #pragma unroll
            for (int mi = 0; mi < 4; ++mi)
                #pragma unroll
                for (int nj = 0; nj < 8; ++nj)
                    MMA_TF32(acc[mi][nj], af[mi], bf[nj]);
        }
    }

    // ---- epilogue: bias (+resid), float2 stores
    #pragma unroll
    for (int mi = 0; mi < 4; ++mi) {
        const int rbase = n0 + wm + mi * 16 + (lane >> 2);
        #pragma unroll
        for (int nj = 0; nj < 8; ++nj) {
            const int col = m0 + wn + nj * 8 + 2 * (lane & 3);
            float2 bb = *(const float2*)(bias + col);
            #pragma unroll
            for (int h = 0; h < 2; ++h) {
                const int r = rbase + h * 8;
                float2 v;
                v.x = acc[mi][nj][2 * h + 0] + bb.x;
                v.y = acc[mi][nj][2 * h + 1] + bb.y;
                size_t off = (size_t)r * ldC + col;
                if (resid) {
                    float2 rr = *(const float2*)(resid + off);
                    v.x += rr.x; v.y += rr.y;
                }
                *(float2*)(C + off) = v;
            }
        }
    }
}

// ---------------------------------------------------------------------------
// Recurrence: chunked parallel scan (3 kernels)
// ---------------------------------------------------------------------------
__global__ void rec_partial(const float* __restrict__ time_decay)
{
    int id = blockIdx.x * blockDim.x + threadIdx.x;   // B*NCH*M threads
    if (id >= B_ * NCH * M_) return;
    int m  = id % M_;
    int ch = (id / M_) % NCH;
    int b  = id / (M_ * NCH);

    float dec = 1.0f / (1.0f + expf(-time_decay[m])) * 0.9f + 0.1f;
    const float* vp = g_v + ((size_t)b * T_ + (size_t)ch * CHUNK) * M_ + m;
    float s = 0.0f;
    #pragma unroll 8
    for (int t = 0; t < CHUNK; ++t)
        s = s * dec + vp[(size_t)t * M_];
    g_part[id] = s;
}

__global__ void rec_combine(const float* __restrict__ memory_state,
                            const float* __restrict__ time_decay,
                            float* __restrict__ next_mem)
{
    int id = blockIdx.x * blockDim.x + threadIdx.x;   // B*M threads
    if (id >= B_ * M_) return;
    int m = id % M_;
    int b = id / M_;

    float dec  = 1.0f / (1.0f + expf(-time_decay[m])) * 0.9f + 0.1f;
    float decC = powf(dec, (float)CHUNK);
    float s = memory_state[id];
    #pragma unroll
    for (int ch = 0; ch < NCH; ++ch) {
        int idx = (b * NCH + ch) * M_ + m;
        g_init[idx] = s;
        s = s * decC + g_part[idx];
    }
    next_mem[id] = s;
}

__global__ void rec_apply(const float* __restrict__ time_decay,
                          const float* __restrict__ time_first)
{
    int id = blockIdx.x * blockDim.x + threadIdx.x;   // B*NCH*M threads
    if (id >= B_ * NCH * M_) return;
    int m  = id % M_;
    int ch = (id / M_) % NCH;
    int b  = id / (M_ * NCH);

    float dec   = 1.0f / (1.0f + expf(-time_decay[m])) * 0.9f + 0.1f;
    float first = 1.0f / (1.0f + expf(-time_first[m]));
    float s = g_init[id];
    float* vp = g_v + ((size_t)b * T_ + (size_t)ch * CHUNK) * M_ + m;
    #pragma unroll 4
    for (int t = 0; t < CHUNK; ++t) {
        float vt = vp[(size_t)t * M_];
        vp[(size_t)t * M_] = vt + s * first;
        s = s * dec + vt;
    }
}

// ---------------------------------------------------------------------------
extern "C" void kernel_launch(void* const* d_in, const int* in_sizes, int n_in,
                              void* d_out, int out_size)
{
    const float* x   = (const float*)d_in[0];  // [B, T, D]
    const float* mem = (const float*)d_in[1];  // [B, M]
    const float* Wv  = (const float*)d_in[2];  // [M, D]
    const float* bv  = (const float*)d_in[3];  // [M]
    const float* Wg  = (const float*)d_in[4];  // [D, D+M]
    const float* bg  = (const float*)d_in[5];  // [D]
    const float* td  = (const float*)d_in[6];  // [M]
    const float* tf  = (const float*)d_in[7];  // [M]
    float* out = (float*)d_out;                // [B,T,D], then [B,M] next_memory

    float* v_ptr = nullptr;
    cudaGetSymbolAddress((void**)&v_ptr, g_v);

    cudaFuncSetAttribute(gemm_mma, cudaFuncAttributeMaxDynamicSharedMemorySize,
                         SMEM_BYTES);

    const int N = B_ * T_;   // 16384

    // Stage 1: v = x @ Wv^T + bv   -> g_v [N, 512]
    {
        dim3 grid(M_ / BN, N / BM);   // (2, 128)
        gemm_mma<<<grid, 256, SMEM_BYTES>>>(x, D_, nullptr, 0,
                                            Wv, bv, nullptr, v_ptr, M_);
    }

    // Stage 2: chunked-scan recurrence (wv overwrites g_v)
    {
        float* next_mem = out + (size_t)B_ * T_ * D_;
        int n1 = B_ * NCH * M_;
        rec_partial<<<(n1 + 255) / 256, 256>>>(td);
        rec_combine<<<(B_ * M_ + 127) / 128, 128>>>(mem, td, next_mem);
        rec_apply<<<(n1 + 255) / 256, 256>>>(td, tf);
    }

    // Stage 3: out = x + concat(x, wv) @ Wg^T + bg   -> out [N, 2048]
    {
        dim3 grid(D_ / BN, N / BM);   // (8, 128)
        gemm_mma<<<grid, 256, SMEM_BYTES>>>(x, D_, v_ptr, M_,
                                            Wg, bg, x, out, D_);
    }
}